// round 13
// baseline (speedup 1.0000x reference)
#include <cuda_runtime.h>
#include <cstdint>

// JANet fused persistent kernel.
// B=256, T=1024, I=128, C=256, O=10, G=2C=512.
//
// Design: 32 clusters x 4 CTAs (128 CTAs, 1 CTA/SM). Cluster c owns batch
// rows [8c, 8c+8). CTA rank q holds the recurrent weight columns
// {q*64+m} U {256+q*64+m} (f and g halves for channels ch = q*64+m) in SMEM
// as float2 pairs, plus the matching input-kernel columns. Each step:
//   z = bias + x[:,t,:] @ Kin + h @ W   (both parts fused, 4 fp32 acc/thread)
//   f = sigmoid(z_f); c = f*c + (1-f)*tanh(z_g)   (fully thread-local!)
//   broadcast c (8B/thread) to all 4 ranks' h[buf^1] via st.shared::cluster
//   one barrier.cluster per step (double-buffered h).
// Epilogue: dense head y = h_final @ dense_w + dense_b, written per rank.

#define Bn 256
#define Tn 1024
#define In 128
#define Cn 256
#define On 10
#define Gn 512

#define NRANK 4
#define ROWS 8          // batch rows per cluster
#define NCTA 128        // 32 clusters * 4
#define THREADS 256
#define MCH 64          // channels per rank

struct Smem {
    float2 Wp[Cn][MCH];      // recurrent weights: (Wf, Wg) pairs   128 KB
    float2 Kin[In][MCH];     // input kernel:      (Kf, Kg) pairs    64 KB
    float  h[2][Cn][ROWS];   // hidden state, double buffered        16 KB
    float  xs[2][In][ROWS];  // staged x(t), double buffered          8 KB
};                           // total 221184 B

__device__ __forceinline__ void cluster_sync() {
    asm volatile("barrier.cluster.arrive.aligned;" ::: "memory");
    asm volatile("barrier.cluster.wait.aligned;" ::: "memory");
}

__device__ __forceinline__ uint32_t smem_u32(const void* p) {
    return (uint32_t)__cvta_generic_to_shared(p);
}

__device__ __forceinline__ void st_cluster_b64(uint32_t laddr, uint32_t rank, uint64_t v) {
    uint32_t raddr;
    asm volatile("mapa.shared::cluster.u32 %0, %1, %2;"
                 : "=r"(raddr) : "r"(laddr), "r"(rank));
    asm volatile("st.shared::cluster.b64 [%0], %1;"
                 :: "r"(raddr), "l"(v) : "memory");
}

__global__ void __launch_bounds__(THREADS, 1) __cluster_dims__(NRANK, 1, 1)
janet_scan_kernel(const float* __restrict__ x,
                  const float* __restrict__ kin,
                  const float* __restrict__ rk,
                  const float* __restrict__ rbias,
                  const float* __restrict__ dw,
                  const float* __restrict__ db,
                  float* __restrict__ out)
{
    extern __shared__ char raw[];
    Smem* s = reinterpret_cast<Smem*>(raw);

    const int tid = threadIdx.x;
    const int cid = blockIdx.x / NRANK;
    uint32_t rank;
    asm("mov.u32 %0, %%cluster_ctarank;" : "=r"(rank));

    const int jf = (int)rank * MCH;   // base of this rank's f-columns

    // ---- load weight slices into SMEM ----
    for (int idx = tid; idx < Cn * MCH; idx += THREADS) {
        int k = idx >> 6, mm = idx & 63;
        s->Wp[k][mm] = make_float2(rk[k * Gn + jf + mm],
                                   rk[k * Gn + Cn + jf + mm]);
    }
    for (int idx = tid; idx < In * MCH; idx += THREADS) {
        int i = idx >> 6, mm = idx & 63;
        s->Kin[i][mm] = make_float2(kin[i * Gn + jf + mm],
                                    kin[i * Gn + Cn + jf + mm]);
    }
    for (int idx = tid; idx < 2 * Cn * ROWS; idx += THREADS)
        (&s->h[0][0][0])[idx] = 0.f;

    // ---- stage x for t=0 (thread: i = tid&127, quad of rows = tid>>7) ----
    const int  pi  = tid & 127;
    const int  prq = tid >> 7;
    const long xrowbase = (long)(cid * ROWS + prq * 4) * (long)(Tn * In);
    {
        float4 v;
        v.x = x[xrowbase + 0L * Tn * In + pi];
        v.y = x[xrowbase + 1L * Tn * In + pi];
        v.z = x[xrowbase + 2L * Tn * In + pi];
        v.w = x[xrowbase + 3L * Tn * In + pi];
        *reinterpret_cast<float4*>(&s->xs[0][pi][prq * 4]) = v;
    }

    // ---- per-thread work assignment: channel m, row pair (r0, r0+1) ----
    const int m  = tid & 63;
    const int rg = tid >> 6;      // 0..3
    const int r0 = rg * 2;
    const float bf = rbias[jf + m];
    const float bg = rbias[Cn + jf + m];
    float c0 = 0.f, c1 = 0.f;

    const float2* Wcol = &s->Wp[0][m];
    const float2* Kcol = &s->Kin[0][m];
    const uint32_t hbase_u32 = smem_u32(&s->h[0][0][0]);
    const int ch = jf + m;        // global channel index this thread owns

    cluster_sync();               // weights + h zeros + x0 visible cluster-wide

    int hb = 0, xb = 0;
    for (int t = 0; t < Tn; ++t) {
        // prefetch x(t+1) — independent of h, hidden under the matvec
        const int  tn = (t + 1 < Tn) ? (t + 1) : t;
        const long pb = (long)tn * In + pi;
        float p0 = __ldg(&x[xrowbase + 0L * Tn * In + pb]);
        float p1 = __ldg(&x[xrowbase + 1L * Tn * In + pb]);
        float p2 = __ldg(&x[xrowbase + 2L * Tn * In + pb]);
        float p3 = __ldg(&x[xrowbase + 3L * Tn * In + pb]);

        float zf0 = bf, zg0 = bg, zf1 = bf, zg1 = bg;

        // input projection part: z += x(t) @ Kin
        const float* xsb = &s->xs[xb][0][r0];
        #pragma unroll 8
        for (int i = 0; i < In; ++i) {
            float2 w  = Kcol[i * MCH];                                   // bcast-free
            float2 xv = *reinterpret_cast<const float2*>(xsb + i * ROWS); // warp bcast
            zf0 = fmaf(xv.x, w.x, zf0);
            zg0 = fmaf(xv.x, w.y, zg0);
            zf1 = fmaf(xv.y, w.x, zf1);
            zg1 = fmaf(xv.y, w.y, zg1);
        }
        // recurrent part: z += h @ W
        const float* hsb = &s->h[hb][0][r0];
        #pragma unroll 8
        for (int k = 0; k < Cn; ++k) {
            float2 w  = Wcol[k * MCH];
            float2 hv = *reinterpret_cast<const float2*>(hsb + k * ROWS);
            zf0 = fmaf(hv.x, w.x, zf0);
            zg0 = fmaf(hv.x, w.y, zg0);
            zf1 = fmaf(hv.y, w.x, zf1);
            zg1 = fmaf(hv.y, w.y, zg1);
        }

        // stage x(t+1) into the other buffer (consumed after next sync)
        *reinterpret_cast<float4*>(&s->xs[xb ^ 1][pi][prq * 4]) =
            make_float4(p0, p1, p2, p3);

        // pointwise gate update — entirely thread-local
        float f0 = 1.f / (1.f + __expf(-zf0));
        float f1 = 1.f / (1.f + __expf(-zf1));
        float g0 = tanhf(zg0);
        float g1 = tanhf(zg1);
        c0 = fmaf(f0, c0 - g0, g0);   // f*c + (1-f)*g
        c1 = fmaf(f1, c1 - g1, g1);

        // broadcast new h (=c) for this channel/row-pair to all 4 ranks
        uint64_t pv = ((uint64_t)__float_as_uint(c1) << 32) |
                       (uint64_t)__float_as_uint(c0);
        uint32_t laddr = hbase_u32 +
            (uint32_t)(((hb ^ 1) * Cn * ROWS + ch * ROWS + r0) * 4);
        #pragma unroll
        for (uint32_t rr = 0; rr < NRANK; ++rr)
            st_cluster_b64(laddr, rr, pv);

        cluster_sync();               // release stores, flip buffers
        hb ^= 1; xb ^= 1;
    }

    // ---- fused dense head: y = h_final @ dw + db ----
    // rank q writes local rows {2q, 2q+1}; every CTA holds the full h.
    const float* hf  = &s->h[hb][0][0];
    const int lane = tid & 31, wrp = tid >> 5;
    for (int task = wrp; task < 2 * On; task += 8) {
        int rloc = (int)rank * 2 + task / On;
        int o    = task % On;
        float acc = 0.f;
        for (int k = lane; k < Cn; k += 32)
            acc += hf[k * ROWS + rloc] * dw[k * On + o];
        #pragma unroll
        for (int off = 16; off; off >>= 1)
            acc += __shfl_down_sync(0xffffffffu, acc, off);
        if (lane == 0)
            out[(cid * ROWS + rloc) * On + o] = acc + db[o];
    }
}

extern "C" void kernel_launch(void* const* d_in, const int* in_sizes, int n_in,
                              void* d_out, int out_size) {
    (void)in_sizes; (void)n_in; (void)out_size;
    const float* x   = (const float*)d_in[0];
    const float* kin = (const float*)d_in[1];
    const float* rk  = (const float*)d_in[2];
    const float* rb  = (const float*)d_in[3];
    const float* dw  = (const float*)d_in[4];
    const float* db  = (const float*)d_in[5];
    float* out = (float*)d_out;

    const size_t smem = sizeof(Smem);   // 221184 bytes
    cudaFuncSetAttribute(janet_scan_kernel,
                         cudaFuncAttributeMaxDynamicSharedMemorySize, (int)smem);
    janet_scan_kernel<<<NCTA, THREADS, smem>>>(x, kin, rk, rb, dw, db, out);
}

// round 14
// speedup vs baseline: 1.0031x; 1.0031x over previous
#include <cuda_runtime.h>
#include <cstdint>

// JANet fused persistent kernel.
// B=256, T=1024, I=128, C=256, O=10, G=2C=512.
//
// Design: 32 clusters x 4 CTAs (128 CTAs, 1 CTA/SM). Cluster c owns batch
// rows [8c, 8c+8). CTA rank q holds the recurrent weight columns
// {q*64+m} U {256+q*64+m} (f and g halves for channels ch = q*64+m) in SMEM
// as float2 pairs, plus the matching input-kernel columns. Each step:
//   z = bias + x[:,t,:] @ Kin + h @ W   (both parts fused, 4 fp32 acc/thread)
//   f = sigmoid(z_f); c = f*c + (1-f)*tanh(z_g)   (fully thread-local!)
//   broadcast c (8B/thread) to all 4 ranks' h[buf^1] via st.shared::cluster
//   one barrier.cluster per step (double-buffered h).
// Epilogue: dense head y = h_final @ dense_w + dense_b, written per rank.

#define Bn 256
#define Tn 1024
#define In 128
#define Cn 256
#define On 10
#define Gn 512

#define NRANK 4
#define ROWS 8          // batch rows per cluster
#define NCTA 128        // 32 clusters * 4
#define THREADS 256
#define MCH 64          // channels per rank

struct Smem {
    float2 Wp[Cn][MCH];      // recurrent weights: (Wf, Wg) pairs   128 KB
    float2 Kin[In][MCH];     // input kernel:      (Kf, Kg) pairs    64 KB
    float  h[2][Cn][ROWS];   // hidden state, double buffered        16 KB
    float  xs[2][In][ROWS];  // staged x(t), double buffered          8 KB
};                           // total 221184 B

__device__ __forceinline__ void cluster_sync() {
    asm volatile("barrier.cluster.arrive.aligned;" ::: "memory");
    asm volatile("barrier.cluster.wait.aligned;" ::: "memory");
}

__device__ __forceinline__ uint32_t smem_u32(const void* p) {
    return (uint32_t)__cvta_generic_to_shared(p);
}

__device__ __forceinline__ void st_cluster_b64(uint32_t laddr, uint32_t rank, uint64_t v) {
    uint32_t raddr;
    asm volatile("mapa.shared::cluster.u32 %0, %1, %2;"
                 : "=r"(raddr) : "r"(laddr), "r"(rank));
    asm volatile("st.shared::cluster.b64 [%0], %1;"
                 :: "r"(raddr), "l"(v) : "memory");
}

__global__ void __launch_bounds__(THREADS, 1) __cluster_dims__(NRANK, 1, 1)
janet_scan_kernel(const float* __restrict__ x,
                  const float* __restrict__ kin,
                  const float* __restrict__ rk,
                  const float* __restrict__ rbias,
                  const float* __restrict__ dw,
                  const float* __restrict__ db,
                  float* __restrict__ out)
{
    extern __shared__ char raw[];
    Smem* s = reinterpret_cast<Smem*>(raw);

    const int tid = threadIdx.x;
    const int cid = blockIdx.x / NRANK;
    uint32_t rank;
    asm("mov.u32 %0, %%cluster_ctarank;" : "=r"(rank));

    const int jf = (int)rank * MCH;   // base of this rank's f-columns

    // ---- load weight slices into SMEM ----
    for (int idx = tid; idx < Cn * MCH; idx += THREADS) {
        int k = idx >> 6, mm = idx & 63;
        s->Wp[k][mm] = make_float2(rk[k * Gn + jf + mm],
                                   rk[k * Gn + Cn + jf + mm]);
    }
    for (int idx = tid; idx < In * MCH; idx += THREADS) {
        int i = idx >> 6, mm = idx & 63;
        s->Kin[i][mm] = make_float2(kin[i * Gn + jf + mm],
                                    kin[i * Gn + Cn + jf + mm]);
    }
    for (int idx = tid; idx < 2 * Cn * ROWS; idx += THREADS)
        (&s->h[0][0][0])[idx] = 0.f;

    // ---- stage x for t=0 (thread: i = tid&127, quad of rows = tid>>7) ----
    const int  pi  = tid & 127;
    const int  prq = tid >> 7;
    const long xrowbase = (long)(cid * ROWS + prq * 4) * (long)(Tn * In);
    {
        float4 v;
        v.x = x[xrowbase + 0L * Tn * In + pi];
        v.y = x[xrowbase + 1L * Tn * In + pi];
        v.z = x[xrowbase + 2L * Tn * In + pi];
        v.w = x[xrowbase + 3L * Tn * In + pi];
        *reinterpret_cast<float4*>(&s->xs[0][pi][prq * 4]) = v;
    }

    // ---- per-thread work assignment: channel m, row pair (r0, r0+1) ----
    const int m  = tid & 63;
    const int rg = tid >> 6;      // 0..3
    const int r0 = rg * 2;
    const float bf = rbias[jf + m];
    const float bg = rbias[Cn + jf + m];
    float c0 = 0.f, c1 = 0.f;

    const float2* Wcol = &s->Wp[0][m];
    const float2* Kcol = &s->Kin[0][m];
    const uint32_t hbase_u32 = smem_u32(&s->h[0][0][0]);
    const int ch = jf + m;        // global channel index this thread owns

    cluster_sync();               // weights + h zeros + x0 visible cluster-wide

    int hb = 0, xb = 0;
    for (int t = 0; t < Tn; ++t) {
        // prefetch x(t+1) — independent of h, hidden under the matvec
        const int  tn = (t + 1 < Tn) ? (t + 1) : t;
        const long pb = (long)tn * In + pi;
        float p0 = __ldg(&x[xrowbase + 0L * Tn * In + pb]);
        float p1 = __ldg(&x[xrowbase + 1L * Tn * In + pb]);
        float p2 = __ldg(&x[xrowbase + 2L * Tn * In + pb]);
        float p3 = __ldg(&x[xrowbase + 3L * Tn * In + pb]);

        float zf0 = bf, zg0 = bg, zf1 = bf, zg1 = bg;

        // input projection part: z += x(t) @ Kin
        const float* xsb = &s->xs[xb][0][r0];
        #pragma unroll 8
        for (int i = 0; i < In; ++i) {
            float2 w  = Kcol[i * MCH];                                   // bcast-free
            float2 xv = *reinterpret_cast<const float2*>(xsb + i * ROWS); // warp bcast
            zf0 = fmaf(xv.x, w.x, zf0);
            zg0 = fmaf(xv.x, w.y, zg0);
            zf1 = fmaf(xv.y, w.x, zf1);
            zg1 = fmaf(xv.y, w.y, zg1);
        }
        // recurrent part: z += h @ W
        const float* hsb = &s->h[hb][0][r0];
        #pragma unroll 8
        for (int k = 0; k < Cn; ++k) {
            float2 w  = Wcol[k * MCH];
            float2 hv = *reinterpret_cast<const float2*>(hsb + k * ROWS);
            zf0 = fmaf(hv.x, w.x, zf0);
            zg0 = fmaf(hv.x, w.y, zg0);
            zf1 = fmaf(hv.y, w.x, zf1);
            zg1 = fmaf(hv.y, w.y, zg1);
        }

        // stage x(t+1) into the other buffer (consumed after next sync)
        *reinterpret_cast<float4*>(&s->xs[xb ^ 1][pi][prq * 4]) =
            make_float4(p0, p1, p2, p3);

        // pointwise gate update — entirely thread-local
        float f0 = 1.f / (1.f + __expf(-zf0));
        float f1 = 1.f / (1.f + __expf(-zf1));
        float g0 = tanhf(zg0);
        float g1 = tanhf(zg1);
        c0 = fmaf(f0, c0 - g0, g0);   // f*c + (1-f)*g
        c1 = fmaf(f1, c1 - g1, g1);

        // broadcast new h (=c) for this channel/row-pair to all 4 ranks
        uint64_t pv = ((uint64_t)__float_as_uint(c1) << 32) |
                       (uint64_t)__float_as_uint(c0);
        uint32_t laddr = hbase_u32 +
            (uint32_t)(((hb ^ 1) * Cn * ROWS + ch * ROWS + r0) * 4);
        #pragma unroll
        for (uint32_t rr = 0; rr < NRANK; ++rr)
            st_cluster_b64(laddr, rr, pv);

        cluster_sync();               // release stores, flip buffers
        hb ^= 1; xb ^= 1;
    }

    // ---- fused dense head: y = h_final @ dw + db ----
    // rank q writes local rows {2q, 2q+1}; every CTA holds the full h.
    const float* hf  = &s->h[hb][0][0];
    const int lane = tid & 31, wrp = tid >> 5;
    for (int task = wrp; task < 2 * On; task += 8) {
        int rloc = (int)rank * 2 + task / On;
        int o    = task % On;
        float acc = 0.f;
        for (int k = lane; k < Cn; k += 32)
            acc += hf[k * ROWS + rloc] * dw[k * On + o];
        #pragma unroll
        for (int off = 16; off; off >>= 1)
            acc += __shfl_down_sync(0xffffffffu, acc, off);
        if (lane == 0)
            out[(cid * ROWS + rloc) * On + o] = acc + db[o];
    }
}

extern "C" void kernel_launch(void* const* d_in, const int* in_sizes, int n_in,
                              void* d_out, int out_size) {
    (void)in_sizes; (void)n_in; (void)out_size;
    const float* x   = (const float*)d_in[0];
    const float* kin = (const float*)d_in[1];
    const float* rk  = (const float*)d_in[2];
    const float* rb  = (const float*)d_in[3];
    const float* dw  = (const float*)d_in[4];
    const float* db  = (const float*)d_in[5];
    float* out = (float*)d_out;

    const size_t smem = sizeof(Smem);   // 221184 bytes
    cudaFuncSetAttribute(janet_scan_kernel,
                         cudaFuncAttributeMaxDynamicSharedMemorySize, (int)smem);
    janet_scan_kernel<<<NCTA, THREADS, smem>>>(x, kin, rk, rb, dw, db, out);
}